// round 10
// baseline (speedup 1.0000x reference)
#include <cuda_runtime.h>
#include <math.h>

// ----------------------------------------------------------------------------
// GAT pipeline: 2x GATConv + global max pool + 3-layer MLP
// CSR gather; layer-2 aggregate-then-transform; f32x2 packed GEMM;
// graph-blocked MLP. N=50000, E=800000 (+N self loops), G=256 graphs
// ----------------------------------------------------------------------------

#define NN 50000
#define EE 800000
#define ET_MAX (EE + NN)
#define GG 256
#define SCAN_B 512
#define NB_MAX 256   // supports n <= 131072

// ---- scratch (device globals; no allocations allowed) ----
__device__ float4   g_h1[NN * 16];      // [N,64] layer-1 features
__device__ float    g_ssrc1[NN * 4];
__device__ float    g_sdst1[NN * 4];
__device__ float    g_inv1[NN * 4];     // per-node softmax 1/sum (4 heads)
__device__ float4   g_h1o[NN * 16];     // [N,64] after agg+bias+ELU
__device__ float4   g_agg64[NN * 16];   // [N,64] layer-2 aggregated (pre-GEMM)
__device__ float    g_ssrc2[NN];
__device__ float    g_sdst2[NN];
__device__ float    g_inv2[NN];
__device__ float    g_psrc[64];         // W2 @ a_src2
__device__ float    g_pdst[64];         // W2 @ a_dst2
__device__ int      g_deg[NN];          // degree (incl self loop)
__device__ int      g_bsum[NB_MAX];     // scan block partials
__device__ int      g_off[NN + 1];      // CSR offsets
__device__ int      g_cur[NN];          // scatter cursors
__device__ int      g_csrc[ET_MAX];     // CSR: source node per edge slot
__device__ float4   g_cw1[ET_MAX];      // CSR: layer1 score -> exp weight (4 heads)
__device__ float    g_cw2[ET_MAX];      // CSR: layer2 score -> exp weight
__device__ unsigned g_pool[GG * 256];
__device__ float    g_z1[GG * 512];
__device__ float    g_z2[GG * 1024];

// ---- helpers ----
__device__ __forceinline__ unsigned fenc(float f) {
    unsigned u = __float_as_uint(f);
    return (u & 0x80000000u) ? ~u : (u | 0x80000000u);
}
__device__ __forceinline__ float fdec(unsigned e) {
    return (e & 0x80000000u) ? __uint_as_float(e & 0x7fffffffu)
                             : __uint_as_float(~e);
}
__device__ __forceinline__ float lrelu(float v) { return v > 0.f ? v : 0.2f * v; }
__device__ __forceinline__ float elu(float v)   { return v > 0.f ? v : expm1f(v); }

// packed f32x2 FMA (sm_103a: 2x fp32 throughput via FFMA2)
__device__ __forceinline__ unsigned long long pack2(float lo, float hi) {
    unsigned long long r;
    asm("mov.b64 %0, {%1, %2};" : "=l"(r) : "f"(lo), "f"(hi));
    return r;
}
__device__ __forceinline__ void ffma2(unsigned long long& d, unsigned long long a,
                                      unsigned long long b) {
    asm("fma.rn.f32x2 %0, %1, %2, %0;" : "+l"(d) : "l"(a), "l"(b));
}
__device__ __forceinline__ void unpack2(unsigned long long v, float& lo, float& hi) {
    asm("mov.b64 {%0, %1}, %2;" : "=f"(lo), "=f"(hi) : "l"(v));
}

// ---- prep: deg=1 (self loop), zero pool ----
__global__ void k_prep(int n) {
    int i = blockIdx.x * blockDim.x + threadIdx.x;
    int stride = gridDim.x * blockDim.x;
    for (int j = i; j < n; j += stride) g_deg[j] = 1;
    for (int j = i; j < GG * 256; j += stride) g_pool[j] = 0u;
}

// ---- project attention vectors through W2 ----
__global__ void k_proj(const float* __restrict__ W2,
                       const float* __restrict__ a_src, const float* __restrict__ a_dst) {
    int w = (blockIdx.x * blockDim.x + threadIdx.x) >> 5;
    int lane = threadIdx.x & 31;
    if (w >= 64) return;
    const float* row = W2 + w * 256;
    float vs = 0.f, vd = 0.f;
    for (int c = lane; c < 256; c += 32) {
        float wv = row[c];
        vs = fmaf(wv, a_src[c], vs);
        vd = fmaf(wv, a_dst[c], vd);
    }
#pragma unroll
    for (int o = 16; o >= 1; o >>= 1) {
        vs += __shfl_down_sync(0xffffffffu, vs, o);
        vd += __shfl_down_sync(0xffffffffu, vd, o);
    }
    if (lane == 0) { g_psrc[w] = vs; g_pdst[w] = vd; }
}

// ---- CSR build ----
__global__ void k_hist(const int* __restrict__ ei, int e) {
    int idx = blockIdx.x * blockDim.x + threadIdx.x;
    if (idx >= e) return;
    atomicAdd(&g_deg[ei[e + idx]], 1);
}

__global__ void k_scanA(int n) {
    __shared__ int sh[SCAN_B];
    int t = threadIdx.x;
    int i = blockIdx.x * SCAN_B + t;
    sh[t] = (i < n) ? g_deg[i] : 0;
    __syncthreads();
#pragma unroll
    for (int o = SCAN_B / 2; o >= 1; o >>= 1) {
        if (t < o) sh[t] += sh[t + o];
        __syncthreads();
    }
    if (t == 0) g_bsum[blockIdx.x] = sh[0];
}

__global__ void k_scanB(int nb) {
    __shared__ int sh[NB_MAX];
    int t = threadIdx.x;
    int v = (t < nb) ? g_bsum[t] : 0;
    sh[t] = v;
    __syncthreads();
#pragma unroll
    for (int o = 1; o < NB_MAX; o <<= 1) {
        int u = (t >= o) ? sh[t - o] : 0;
        __syncthreads();
        sh[t] += u;
        __syncthreads();
    }
    if (t < nb) g_bsum[t] = sh[t] - v;
}

__global__ void k_scanC(int n) {
    __shared__ int sh[SCAN_B];
    int t = threadIdx.x;
    int i = blockIdx.x * SCAN_B + t;
    int v = (i < n) ? g_deg[i] : 0;
    sh[t] = v;
    __syncthreads();
#pragma unroll
    for (int o = 1; o < SCAN_B; o <<= 1) {
        int u = (t >= o) ? sh[t - o] : 0;
        __syncthreads();
        sh[t] += u;
        __syncthreads();
    }
    int excl = sh[t] - v + g_bsum[blockIdx.x];
    if (i < n) {
        g_off[i] = excl;
        g_cur[i] = excl;
        if (i == n - 1) g_off[n] = excl + v;
    }
}

__global__ void k_scatter(const int* __restrict__ ei, int e, int n) {
    int idx = blockIdx.x * blockDim.x + threadIdx.x;
    int et = e + n;
    if (idx >= et) return;
    int s, d;
    if (idx < e) { s = ei[idx]; d = ei[e + idx]; } else { s = d = idx - e; }
    int pos = atomicAdd(&g_cur[d], 1);
    g_csrc[pos] = s;
}

// ---- layer1 GEMM [N,27]x[27,64] + attention scores ----
// 32 nodes/block; W1 column in regs; x rows padded to 28 floats (float4 LDS).
__global__ void k_gemm1(const float* __restrict__ x, const float* __restrict__ W1,
                        const float* __restrict__ a_src, const float* __restrict__ a_dst,
                        int n) {
    __shared__ float xs[32 * 28];
    int t = threadIdx.x;
    int col = t & 63, slot = t >> 6;     // 4 slots
    float wcol[28];
#pragma unroll
    for (int k = 0; k < 27; k++) wcol[k] = W1[k * 64 + col];
    wcol[27] = 0.f;
    float asv = a_src[col], adv = a_dst[col];
    int base = blockIdx.x * 32;
    for (int i = t; i < 32 * 27; i += 256) {
        int nn = base + i / 27;
        xs[(i / 27) * 28 + i % 27] = (nn < n) ? x[nn * 27 + i % 27] : 0.f;
    }
    if (t < 32) xs[t * 28 + 27] = 0.f;
    __syncthreads();
#pragma unroll
    for (int g = 0; g < 8; g++) {
        int nl = g * 4 + slot;
        int node = base + nl;
        const float4* xr4 = (const float4*)(xs + nl * 28);
        float h = 0.f;
#pragma unroll
        for (int j = 0; j < 7; j++) {
            float4 xv = xr4[j];
            h = fmaf(xv.x, wcol[4 * j + 0], h);
            h = fmaf(xv.y, wcol[4 * j + 1], h);
            h = fmaf(xv.z, wcol[4 * j + 2], h);
            h = fmaf(xv.w, wcol[4 * j + 3], h);
        }
        float vs = h * asv, vd = h * adv;
#pragma unroll
        for (int o = 8; o >= 1; o >>= 1) {
            vs += __shfl_down_sync(0xffffffffu, vs, o, 16);
            vd += __shfl_down_sync(0xffffffffu, vd, o, 16);
        }
        if (node < n) {
            ((float*)g_h1)[node * 64 + col] = h;
            if ((col & 15) == 0) {
                g_ssrc1[node * 4 + (col >> 4)] = vs;
                g_sdst1[node * 4 + (col >> 4)] = vd;
            }
        }
    }
}

// ---- layer1 softmax: scores -> exp weights + per-node inv (2 passes) ----
__global__ void k_soft1(int n) {
    int w = (blockIdx.x * blockDim.x + threadIdx.x) >> 5;
    int lane = threadIdx.x & 31;
    if (w >= n) return;
    int off = g_off[w], end = g_off[w + 1];
    float4 sd = *(const float4*)&g_sdst1[w * 4];
    float4 mx = make_float4(-1e30f, -1e30f, -1e30f, -1e30f);
    for (int p = off + lane; p < end; p += 32) {
        int s = g_csrc[p];
        float4 ss = *(const float4*)&g_ssrc1[s * 4];
        float4 a = make_float4(lrelu(ss.x + sd.x), lrelu(ss.y + sd.y),
                               lrelu(ss.z + sd.z), lrelu(ss.w + sd.w));
        g_cw1[p] = a;
        mx.x = fmaxf(mx.x, a.x); mx.y = fmaxf(mx.y, a.y);
        mx.z = fmaxf(mx.z, a.z); mx.w = fmaxf(mx.w, a.w);
    }
#pragma unroll
    for (int o = 16; o >= 1; o >>= 1) {
        mx.x = fmaxf(mx.x, __shfl_xor_sync(0xffffffffu, mx.x, o));
        mx.y = fmaxf(mx.y, __shfl_xor_sync(0xffffffffu, mx.y, o));
        mx.z = fmaxf(mx.z, __shfl_xor_sync(0xffffffffu, mx.z, o));
        mx.w = fmaxf(mx.w, __shfl_xor_sync(0xffffffffu, mx.w, o));
    }
    float4 sum = make_float4(0.f, 0.f, 0.f, 0.f);
    for (int p = off + lane; p < end; p += 32) {
        float4 a = g_cw1[p];
        float4 wv = make_float4(__expf(a.x - mx.x), __expf(a.y - mx.y),
                                __expf(a.z - mx.z), __expf(a.w - mx.w));
        g_cw1[p] = wv;
        sum.x += wv.x; sum.y += wv.y; sum.z += wv.z; sum.w += wv.w;
    }
#pragma unroll
    for (int o = 16; o >= 1; o >>= 1) {
        sum.x += __shfl_xor_sync(0xffffffffu, sum.x, o);
        sum.y += __shfl_xor_sync(0xffffffffu, sum.y, o);
        sum.z += __shfl_xor_sync(0xffffffffu, sum.z, o);
        sum.w += __shfl_xor_sync(0xffffffffu, sum.w, o);
    }
    if (lane == 0) {
        float4 inv = make_float4(1.f / (sum.x + 1e-16f), 1.f / (sum.y + 1e-16f),
                                 1.f / (sum.z + 1e-16f), 1.f / (sum.w + 1e-16f));
        *(float4*)&g_inv1[w * 4] = inv;
    }
}

// ---- layer1 gather-aggregate + bias + ELU + fused layer2 scores ----
__global__ void k_gagg1(const float* __restrict__ b1, int n) {
    int gid = blockIdx.x * blockDim.x + threadIdx.x;
    int node = gid >> 4;
    if (node >= n) return;
    int q = gid & 15;
    int head = q >> 2;
    float inv = g_inv1[node * 4 + head];
    int off = g_off[node], end = g_off[node + 1];
    float4 acc = make_float4(0.f, 0.f, 0.f, 0.f);
    for (int p = off; p < end; p++) {
        int s = g_csrc[p];
        float c = ((const float*)g_cw1)[p * 4 + head] * inv;
        float4 h = g_h1[s * 16 + q];
        acc.x = fmaf(c, h.x, acc.x); acc.y = fmaf(c, h.y, acc.y);
        acc.z = fmaf(c, h.z, acc.z); acc.w = fmaf(c, h.w, acc.w);
    }
    float4 b = ((const float4*)b1)[q];
    acc.x = elu(acc.x + b.x); acc.y = elu(acc.y + b.y);
    acc.z = elu(acc.z + b.z); acc.w = elu(acc.w + b.w);
    g_h1o[node * 16 + q] = acc;
    float4 ps = ((const float4*)g_psrc)[q];
    float4 pd = ((const float4*)g_pdst)[q];
    float vs = acc.x * ps.x + acc.y * ps.y + acc.z * ps.z + acc.w * ps.w;
    float vd = acc.x * pd.x + acc.y * pd.y + acc.z * pd.z + acc.w * pd.w;
#pragma unroll
    for (int o = 8; o >= 1; o >>= 1) {
        vs += __shfl_down_sync(0xffffffffu, vs, o, 16);
        vd += __shfl_down_sync(0xffffffffu, vd, o, 16);
    }
    if (q == 0) { g_ssrc2[node] = vs; g_sdst2[node] = vd; }
}

// ---- layer2 softmax (2 passes + inv) ----
__global__ void k_soft2(int n) {
    int w = (blockIdx.x * blockDim.x + threadIdx.x) >> 5;
    int lane = threadIdx.x & 31;
    if (w >= n) return;
    int off = g_off[w], end = g_off[w + 1];
    float sd = g_sdst2[w];
    float mx = -1e30f;
    for (int p = off + lane; p < end; p += 32) {
        float a = lrelu(g_ssrc2[g_csrc[p]] + sd);
        g_cw2[p] = a;
        mx = fmaxf(mx, a);
    }
#pragma unroll
    for (int o = 16; o >= 1; o >>= 1)
        mx = fmaxf(mx, __shfl_xor_sync(0xffffffffu, mx, o));
    float sum = 0.f;
    for (int p = off + lane; p < end; p += 32) {
        float wv = __expf(g_cw2[p] - mx);
        g_cw2[p] = wv;
        sum += wv;
    }
#pragma unroll
    for (int o = 16; o >= 1; o >>= 1)
        sum += __shfl_xor_sync(0xffffffffu, sum, o);
    if (lane == 0) g_inv2[w] = 1.f / (sum + 1e-16f);
}

// ---- layer2 aggregate in 64-dim ----
__global__ void k_gagg2(int n) {
    int gid = blockIdx.x * blockDim.x + threadIdx.x;
    int node = gid >> 4;
    if (node >= n) return;
    int q = gid & 15;
    float inv = g_inv2[node];
    int off = g_off[node], end = g_off[node + 1];
    float4 acc = make_float4(0.f, 0.f, 0.f, 0.f);
    for (int p = off; p < end; p++) {
        int s = g_csrc[p];
        float c = g_cw2[p] * inv;
        float4 h = g_h1o[s * 16 + q];
        acc.x = fmaf(c, h.x, acc.x); acc.y = fmaf(c, h.y, acc.y);
        acc.z = fmaf(c, h.z, acc.z); acc.w = fmaf(c, h.w, acc.w);
    }
    g_agg64[node * 16 + q] = acc;
}

// ---- layer2 post-GEMM [N,64]x[64,256] via packed f32x2; +bias+ELU+pool ----
// 32 nodes/block packed as 16 node-pairs per f32x2 accumulator.
__global__ void k_gemm2p(const float* __restrict__ W2, const float* __restrict__ b2,
                         const int* __restrict__ batch, int n) {
    __shared__ float Wsh[32 * 256];       // 32 KB chunk
    __shared__ float2 xsp[64][16];        // [k][node-pair] = 8 KB
    int t = threadIdx.x;  // 256 threads = 256 cols
    int n0 = blockIdx.x * 32;
    unsigned long long acc[16];
#pragma unroll
    for (int p = 0; p < 16; p++) acc[p] = 0ull;
    for (int i = t; i < 32 * 64; i += 256) {
        int nl = i >> 6, k = i & 63;
        int nn = n0 + nl;
        float v = (nn < n) ? ((const float*)g_agg64)[nn * 64 + k] : 0.f;
        ((float*)&xsp[k][nl >> 1])[nl & 1] = v;
    }
    for (int kc = 0; kc < 2; kc++) {
        __syncthreads();
        for (int i = t; i < 32 * 256; i += 256) Wsh[i] = W2[kc * 32 * 256 + i];
        __syncthreads();
#pragma unroll
        for (int k = 0; k < 32; k++) {
            float w = Wsh[k * 256 + t];
            unsigned long long w2 = pack2(w, w);
            const unsigned long long* xp =
                (const unsigned long long*)&xsp[kc * 32 + k][0];
#pragma unroll
            for (int p = 0; p < 16; p++) ffma2(acc[p], xp[p], w2);
        }
    }
    float bb = b2[t];
#pragma unroll
    for (int p = 0; p < 16; p++) {
        float lo, hi;
        unpack2(acc[p], lo, hi);
        int na = n0 + 2 * p, nb2 = na + 1;
        if (na < n)  atomicMax(&g_pool[batch[na] * 256 + t],  fenc(elu(lo + bb)));
        if (nb2 < n) atomicMax(&g_pool[batch[nb2] * 256 + t], fenc(elu(hi + bb)));
    }
}

// ---- MLP l1: [G,256]x[256,512]+relu, graph-blocked (8 graphs/block) ----
__global__ void k_l1(const float* __restrict__ Wl1, const float* __restrict__ bl1) {
    __shared__ float ps[8][256];
    int t = threadIdx.x;                     // 256 threads
    int col = blockIdx.x * 256 + t;          // 2 col blocks
    int g0 = blockIdx.y * 8;
    for (int i = t; i < 8 * 256; i += 256)
        ps[i >> 8][i & 255] = fdec(g_pool[(g0 + (i >> 8)) * 256 + (i & 255)]);
    __syncthreads();
    float acc[8] = {0.f, 0.f, 0.f, 0.f, 0.f, 0.f, 0.f, 0.f};
    for (int k = 0; k < 256; k++) {
        float w = Wl1[k * 512 + col];
#pragma unroll
        for (int gl = 0; gl < 8; gl++) acc[gl] = fmaf(ps[gl][k], w, acc[gl]);
    }
    float bb = bl1[col];
#pragma unroll
    for (int gl = 0; gl < 8; gl++) {
        float v = acc[gl] + bb;
        g_z1[(g0 + gl) * 512 + col] = v > 0.f ? v : 0.f;
    }
}

// ---- MLP l2: [G,512]x[512,1024]+relu, graph-blocked (8 graphs/block) ----
__global__ void k_l2(const float* __restrict__ Wl2, const float* __restrict__ bl2) {
    __shared__ float ps[8][512];
    int t = threadIdx.x;                     // 256 threads
    int col = blockIdx.x * 256 + t;          // 4 col blocks
    int g0 = blockIdx.y * 8;
    for (int i = t; i < 8 * 512; i += 256)
        ps[i >> 9][i & 511] = g_z1[(g0 + (i >> 9)) * 512 + (i & 511)];
    __syncthreads();
    float acc[8] = {0.f, 0.f, 0.f, 0.f, 0.f, 0.f, 0.f, 0.f};
    for (int k = 0; k < 512; k++) {
        float w = Wl2[k * 1024 + col];
#pragma unroll
        for (int gl = 0; gl < 8; gl++) acc[gl] = fmaf(ps[gl][k], w, acc[gl]);
    }
    float bb = bl2[col];
#pragma unroll
    for (int gl = 0; gl < 8; gl++) {
        float v = acc[gl] + bb;
        g_z2[(g0 + gl) * 1024 + col] = v > 0.f ? v : 0.f;
    }
}

// ---- MLP l3: [G,1024]x[1024,4] -> d_out ----
__global__ void k_l3(const float* __restrict__ Wl3, const float* __restrict__ bl3,
                     float* __restrict__ out) {
    int g = blockIdx.x;
    int wj = threadIdx.x >> 5;
    int lane = threadIdx.x & 31;
    float acc = 0.f;
    for (int k = lane; k < 1024; k += 32)
        acc = fmaf(g_z2[g * 1024 + k], Wl3[k * 4 + wj], acc);
#pragma unroll
    for (int o = 16; o >= 1; o >>= 1) acc += __shfl_down_sync(0xffffffffu, acc, o);
    if (lane == 0) out[g * 4 + wj] = acc + bl3[wj];
}

// ----------------------------------------------------------------------------
extern "C" void kernel_launch(void* const* d_in, const int* in_sizes, int n_in,
                              void* d_out, int out_size) {
    const float* x      = (const float*)d_in[0];
    const int*   ei     = (const int*)d_in[1];
    const int*   batch  = (const int*)d_in[2];
    const float* W1     = (const float*)d_in[3];
    const float* a_src1 = (const float*)d_in[4];
    const float* a_dst1 = (const float*)d_in[5];
    const float* b1     = (const float*)d_in[6];
    const float* W2     = (const float*)d_in[7];
    const float* a_src2 = (const float*)d_in[8];
    const float* a_dst2 = (const float*)d_in[9];
    const float* b2     = (const float*)d_in[10];
    const float* Wl1    = (const float*)d_in[11];
    const float* bl1    = (const float*)d_in[12];
    const float* Wl2    = (const float*)d_in[13];
    const float* bl2    = (const float*)d_in[14];
    const float* Wl3    = (const float*)d_in[15];
    const float* bl3    = (const float*)d_in[16];

    int n = in_sizes[0] / 27;
    int e = in_sizes[1] / 2;
    int et = e + n;
    int nb = (n + SCAN_B - 1) / SCAN_B;

    k_prep<<<256, 256>>>(n);
    k_hist<<<(e + 255) / 256, 256>>>(ei, e);
    k_proj<<<4, 512>>>(W2, a_src2, a_dst2);
    k_gemm1<<<(n + 31) / 32, 256>>>(x, W1, a_src1, a_dst1, n);
    k_scanA<<<nb, SCAN_B>>>(n);
    k_scanB<<<1, NB_MAX>>>(nb);
    k_scanC<<<nb, SCAN_B>>>(n);
    k_scatter<<<(et + 255) / 256, 256>>>(ei, e, n);
    k_soft1<<<(n * 32 + 255) / 256, 256>>>(n);
    k_gagg1<<<(n * 16 + 255) / 256, 256>>>(b1, n);
    k_soft2<<<(n * 32 + 255) / 256, 256>>>(n);
    k_gagg2<<<(n * 16 + 255) / 256, 256>>>(n);
    k_gemm2p<<<(n + 31) / 32, 256>>>(W2, b2, batch, n);
    {
        dim3 gl1(2, 32);  k_l1<<<gl1, 256>>>(Wl1, bl1);
        dim3 gl2(4, 32);  k_l2<<<gl2, 256>>>(Wl2, bl2);
        k_l3<<<GG, 128>>>(Wl3, bl3, (float*)d_out);
    }
}